// round 15
// baseline (speedup 1.0000x reference)
#include <cuda_runtime.h>
#include <cuda_fp16.h>
#include <math.h>

// Problem constants
#define BB 8
#define TT 2048
#define CC 1024
#define DD 64
#define MM (BB*TT)          // 16384 rows

// ---------------------------------------------------------------------------
// Global scratch, all fp16 fragment layouts (allocation-free __device__)
// A-frag (m16k16, 128 u32/tile); B-frag (k16n8, 64 u32/tile)
// ---------------------------------------------------------------------------
__device__ unsigned g_qf [MM*DD/2];   // q,  A-frag per 64-token block (scale*log2e folded)
__device__ unsigned g_kf [MM*DD/2];   // k,  B-frag: [tb][(keyTile8)(dTile4)][64]   (k=d,n=key)
__device__ unsigned g_vf [MM*DD/2];   // v,  B-frag: [tb][(dTile8)(keyTile4)][64]   (k=key,n=d)
__device__ unsigned g_wpef[DD*CC/2];      // Wp_eff: [nt(128)][kt(4)][64]
__device__ unsigned g_wqkvf[3*CC*DD/2];   // W q|k|v: [ktG(64)][mat*8+nt(24)][64]

// ---------------------------------------------------------------------------
// helpers
// ---------------------------------------------------------------------------
__device__ __forceinline__ unsigned f2h2(float a, float b) {
    __half2 h = __float22half2_rn(make_float2(a, b));
    return *reinterpret_cast<unsigned*>(&h);
}
__device__ __forceinline__ float ex2(float x) {
    float y; asm("ex2.approx.f32 %0, %1;" : "=f"(y) : "f"(x)); return y;
}
__device__ __forceinline__ void mma16(float* d, const unsigned* a, unsigned b0, unsigned b1) {
    asm volatile("mma.sync.aligned.m16n8k16.row.col.f32.f16.f16.f32 "
                 "{%0,%1,%2,%3},{%4,%5,%6,%7},{%8,%9},{%0,%1,%2,%3};"
                 : "+f"(d[0]), "+f"(d[1]), "+f"(d[2]), "+f"(d[3])
                 : "r"(a[0]), "r"(a[1]), "r"(a[2]), "r"(a[3]), "r"(b0), "r"(b1));
}
__device__ __forceinline__ int aswz(int L) { return L ^ (L >> 3); }
// A-frag u32 address within a 64row x 64k block (4x4 tiles of 132 u, swizzled)
__device__ __forceinline__ int a_addr(int row, int k) {    // k even
    return ((row >> 4)*4 + (k >> 4)) * 132
         + aswz(((row & 7) << 2) | ((k >> 1) & 3)) * 4
         + ((row >> 3) & 1) + (((k >> 3) & 1) << 1);
}
__device__ __forceinline__ int bf_idx(int k, int n) {      // k even
    return ((((n & 7) << 2) | ((k >> 1) & 3)) << 1) + ((k >> 3) & 1);
}
__device__ __forceinline__ void bar64(int id) {
    asm volatile("bar.sync %0, %1;" :: "r"(id), "r"(64) : "memory");
}
__device__ __forceinline__ void cpa16(unsigned saddr, const void* g) {
    asm volatile("cp.async.cg.shared.global [%0], [%1], 16;" :: "r"(saddr), "l"(g));
}
#define CP_COMMIT() asm volatile("cp.async.commit_group;" ::: "memory")
#define CP_WAIT0()  asm volatile("cp.async.wait_group 0;" ::: "memory")

// ---------------------------------------------------------------------------
// Kernel 1 (prep): Wp_eff fold + weights -> fp16 B-frag layouts (R10 version).
// ---------------------------------------------------------------------------
__global__ __launch_bounds__(256) void prep_kernel(const float* __restrict__ Wq,
                                                   const float* __restrict__ Wk,
                                                   const float* __restrict__ Wv,
                                                   const float* __restrict__ Wp) {
    int idx2 = blockIdx.x * 256 + threadIdx.x;     // 0..65535
    int pid = idx2 >> 1, hh = idx2 & 1;
    {
        int d0 = (pid >> 10) * 2, j = pid & 1023;
        float s0 = 0.f, s1 = 0.f;
#pragma unroll
        for (int h = hh*8; h < hh*8 + 8; h++) {
            s0 += Wp[(h*64 + d0    )*1024 + j];
            s1 += Wp[(h*64 + d0 + 1)*1024 + j];
        }
        s0 += __shfl_xor_sync(0xffffffffu, s0, 1);
        s1 += __shfl_xor_sync(0xffffffffu, s1, 1);
        if (!hh)
            g_wpef[(j >> 3)*256 + (d0 >> 4)*64 + bf_idx(d0, j)] = f2h2(s0, s1);
    }
    {
        const float qs = 0.03125f * 1.44269504088896f;
        int c0 = (pid >> 6) * 2, n = pid & 63;
        int ba = (c0 >> 4)*1536 + (n >> 3)*64 + bf_idx(c0, n);
        if (!hh) {
            g_wqkvf[ba]        = f2h2(Wq[c0*64 + n]*qs, Wq[(c0+1)*64 + n]*qs);
            g_wqkvf[ba + 512]  = f2h2(Wk[c0*64 + n],    Wk[(c0+1)*64 + n]);
        } else {
            g_wqkvf[ba + 1024] = f2h2(Wv[c0*64 + n],    Wv[(c0+1)*64 + n]);
        }
    }
}

// ---------------------------------------------------------------------------
// Kernel 2: fused QKV (EXACT R10 version, 78.3us baseline).
// ---------------------------------------------------------------------------
__global__ __launch_bounds__(256, 2) void qkv_kernel(const float* __restrict__ x) {
    extern __shared__ unsigned smu[];
    const int t = threadIdx.x, lane = t & 31, w = t >> 5;
    const int rowBase = blockIdx.x * 64;
    const int m0t = (w & 1) * 2;
    const int ntb = (w >> 1) * 6;

    float acc[2][6][4];
#pragma unroll
    for (int mi = 0; mi < 2; mi++)
#pragma unroll
        for (int ni = 0; ni < 6; ni++)
#pragma unroll
            for (int r = 0; r < 4; r++) acc[mi][ni][r] = 0.f;

    const int arow = t >> 2, acol4 = (t & 3) * 4;
    float4 xr[4];
#pragma unroll
    for (int q = 0; q < 4; q++)
        xr[q] = *(const float4*)&x[(size_t)(rowBase + arow)*CC + q*16 + acol4];
#pragma unroll
    for (int q = 0; q < 4; q++) {
        int k = q*16 + acol4;
        smu[a_addr(arow, k)]     = f2h2(xr[q].x, xr[q].y);
        smu[a_addr(arow, k + 2)] = f2h2(xr[q].z, xr[q].w);
    }
    __syncthreads();

    for (int k0 = 0; k0 < CC; k0 += 64) {
        const unsigned* As = smu + ((k0 >> 6) & 1) * 2112;
        const int ktG = k0 >> 4;
        const bool more = (k0 + 64) < CC;
        if (more) {
#pragma unroll
            for (int q = 0; q < 4; q++)
                xr[q] = *(const float4*)&x[(size_t)(rowBase + arow)*CC + k0 + 64 + q*16 + acol4];
        }
#pragma unroll
        for (int ks = 0; ks < 4; ks++) {
            uint4 v0 = *(const uint4*)&As[(m0t*4 + ks)*132 + aswz(lane)*4];
            uint4 v1 = *(const uint4*)&As[((m0t+1)*4 + ks)*132 + aswz(lane)*4];
            unsigned a0[4] = {v0.x, v0.y, v0.z, v0.w};
            unsigned a1[4] = {v1.x, v1.y, v1.z, v1.w};
#pragma unroll
            for (int ni = 0; ni < 6; ni++) {
                uint2 b = *(const uint2*)&g_wqkvf[(ktG + ks)*1536 + (ntb + ni)*64 + 2*lane];
                mma16(acc[0][ni], a0, b.x, b.y);
                mma16(acc[1][ni], a1, b.x, b.y);
            }
        }
        if (more) {
            unsigned* An = smu + (((k0 >> 6) & 1) ^ 1) * 2112;
#pragma unroll
            for (int q = 0; q < 4; q++) {
                int k = q*16 + acol4;
                An[a_addr(arow, k)]     = f2h2(xr[q].x, xr[q].y);
                An[a_addr(arow, k + 2)] = f2h2(xr[q].z, xr[q].w);
            }
        }
        __syncthreads();
    }

    // ---- epilogue: stage C-frags into fp16 operand layouts ----
    __half* vstage = (__half*)(smu + 6272);
#pragma unroll
    for (int mi = 0; mi < 2; mi++) {
#pragma unroll
        for (int ni = 0; ni < 6; ni++) {
            int row0 = (w & 1)*32 + mi*16 + (lane >> 2);
            int col0 = (ntb + ni)*8 + 2*(lane & 3);
            int mat = col0 >> 6;
            if (mat == 0) {
                smu[a_addr(row0,     col0)] = f2h2(acc[mi][ni][0], acc[mi][ni][1]);
                smu[a_addr(row0 + 8, col0)] = f2h2(acc[mi][ni][2], acc[mi][ni][3]);
            } else if (mat == 1) {
                int d = col0 - 64;
                int t0 = ((row0 >> 3)*4 + (d >> 4))*64;
                smu[4224 + t0       + bf_idx(d, row0)] = f2h2(acc[mi][ni][0], acc[mi][ni][1]);
                smu[4224 + t0 + 256 + bf_idx(d, row0)] = f2h2(acc[mi][ni][2], acc[mi][ni][3]);
            } else {
                int d = col0 - 128;
                int u0 = (d >> 3)*256 + (row0 >> 4)*64;
                vstage[(u0 + bf_idx(row0 & 63, d))*2     + (row0 & 1)] = __float2half_rn(acc[mi][ni][0]);
                vstage[(u0 + bf_idx(row0 & 63, d+1))*2   + (row0 & 1)] = __float2half_rn(acc[mi][ni][1]);
                int r8 = row0 + 8;
                int u8 = (d >> 3)*256 + (r8 >> 4)*64;
                vstage[(u8 + bf_idx(r8 & 63, d))*2   + (r8 & 1)] = __float2half_rn(acc[mi][ni][2]);
                vstage[(u8 + bf_idx(r8 & 63, d+1))*2 + (r8 & 1)] = __float2half_rn(acc[mi][ni][3]);
            }
        }
    }
    __syncthreads();

    const size_t rb = blockIdx.x;
#pragma unroll
    for (int j = 0; j < 2; j++) {
        int tile = w*2 + j;
        uint4 v = *(const uint4*)&smu[tile*132 + aswz(lane)*4];
        *(uint4*)&g_qf[rb*2048 + tile*128 + lane*4] = v;
    }
#pragma unroll
    for (int j = 0; j < 2; j++) {
        int u = t + 256*j;
        *(uint4*)&g_kf[rb*2048 + 4*u] = *(const uint4*)&smu[4224 + 4*u];
    }
#pragma unroll
    for (int j = 0; j < 2; j++) {
        int u = t + 256*j;
        *(uint4*)&g_vf[rb*2048 + 4*u] = *(const uint4*)&smu[6272 + 4*u];
    }
}

// ---------------------------------------------------------------------------
// Kernel 3: causal flash attention + FUSED PROJECTION (R14 winner) with the
// mainloop KV copy switched to cp.async.cg double-buffering (no RF round-trip,
// no kr/vr registers). Pipeline: issue tile it+1 at loop head, compute tile it,
// wait_group 0 AFTER compute (copy hides behind mma+ex2). Wp_eff (128 KB)
// still streamed fire-and-forget at start; absorbed by the first in-loop wait.
// smem (u32): K 0/2048, V 4096/6144, Ps @8192 (2112), lsh @10304 (128),
//             Wps @10432 (32768), bias @43200 (1024). total 44224 u32.
// ---------------------------------------------------------------------------
__global__ __launch_bounds__(256, 1) void attn_kernel(float* __restrict__ out,
                                                      const float* __restrict__ bp) {
    extern __shared__ unsigned smu[];
    unsigned* Ps = smu + 8192;
    float* lsh = (float*)(smu + 10304);
    unsigned* Wps = smu + 10432;
    float* bias_sh = (float*)(smu + 43200);
    float* scr = (float*)smu;

    const int t = threadIdx.x, lane = t & 31, w = t >> 5;
    const int bid = blockIdx.x;
    const int batch = bid & 7;
    const int qt = 31 - (bid >> 3);       // big q-tiles first (LPT)
    const int half_id = w & 1;
    const int mt = w >> 1;
    const int rl = lane >> 2;
    const int rA = mt*16 + rl, rB = rA + 8;
    const int colb = half_id * 32;
    const int barid = 1 + mt;

    const size_t qrb = batch*32 + qt;
    const int ntiles = qt + 1;
    const unsigned sbase = (unsigned)__cvta_generic_to_shared(smu);

    // KV tile copy issuer: tile index -> buffer (it & 1), 4x16B per thread
    auto issue_kv = [&](int tile, int buf) {
        size_t gb = (size_t)(batch*32 + tile)*2048;
#pragma unroll
        for (int j = 0; j < 2; j++) {
            unsigned off = 4*(t + 256*j);
            cpa16(sbase + (buf*2048 + off)*4,          &g_kf[gb + off]);
            cpa16(sbase + (4096 + buf*2048 + off)*4,   &g_vf[gb + off]);
        }
        CP_COMMIT();
    };

    // issue KV tile 0, then fire-and-forget Wp_eff copy (ordered after tile 0)
    issue_kv(0, 0);
    {
        const unsigned wbase = (unsigned)__cvta_generic_to_shared(Wps);
#pragma unroll
        for (int j = 0; j < 32; j++) {
            int u = t + 256*j;            // uint4 index, 0..8191
            cpa16(wbase + u*16, &g_wpef[4*u]);
        }
        CP_COMMIT();
    }
    // bias -> smem
    *(float4*)&bias_sh[t*4] = *(const float4*)&bp[t*4];

    // Q fragments: gmem -> registers (4 k16 tiles)
    unsigned qf[4][4];
#pragma unroll
    for (int kt = 0; kt < 4; kt++) {
        uint4 v = *(const uint4*)&g_qf[qrb*2048 + (mt*4 + kt)*128 + lane*4];
        qf[kt][0] = v.x; qf[kt][1] = v.y; qf[kt][2] = v.z; qf[kt][3] = v.w;
    }

    float lAr = 0.f, lBr = 0.f;
    float oacc[8][4];
#pragma unroll
    for (int ni = 0; ni < 8; ni++)
#pragma unroll
        for (int r = 0; r < 4; r++) oacc[ni][r] = 0.f;

    // wait for tile 0 (group 1 = Wp may still be pending: allow it)
    asm volatile("cp.async.wait_group 1;" ::: "memory");
    __syncthreads();

    for (int it = 0; it < ntiles; it++) {
        const unsigned* Kb = smu + (it & 1)*2048;
        const unsigned* Vb = smu + 4096 + (it & 1)*2048;
        const bool more = (it + 1) < ntiles;

        // issue next tile first (overlaps with this tile's compute)
        if (more) issue_kv(it + 1, (it + 1) & 1);

        float sacc[4][4];
#pragma unroll
        for (int ni = 0; ni < 4; ni++)
#pragma unroll
            for (int r = 0; r < 4; r++) sacc[ni][r] = 0.f;
#pragma unroll
        for (int ks = 0; ks < 4; ks++)
#pragma unroll
            for (int ni = 0; ni < 4; ni++) {
                uint2 b = *(const uint2*)&Kb[((half_id*4 + ni)*4 + ks)*64 + 2*lane];
                mma16(sacc[ni], qf[ks], b.x, b.y);
            }

        if (it == ntiles - 1) {
#pragma unroll
            for (int ni = 0; ni < 4; ni++) {
                int c0 = colb + ni*8 + 2*(lane & 3);
                if (c0     > rA) sacc[ni][0] = -1e30f;
                if (c0 + 1 > rA) sacc[ni][1] = -1e30f;
                if (c0     > rB) sacc[ni][2] = -1e30f;
                if (c0 + 1 > rB) sacc[ni][3] = -1e30f;
            }
        }

        unsigned pa[2][4];
#pragma unroll
        for (int ni = 0; ni < 4; ni++) {
            float p0 = ex2(sacc[ni][0]);
            float p1 = ex2(sacc[ni][1]);
            float p2 = ex2(sacc[ni][2]);
            float p3 = ex2(sacc[ni][3]);
            lAr += p0 + p1;
            lBr += p2 + p3;
            pa[ni >> 1][(ni & 1)*2]     = f2h2(p0, p1);
            pa[ni >> 1][(ni & 1)*2 + 1] = f2h2(p2, p3);
        }

#pragma unroll
        for (int p = 0; p < 2; p++)
#pragma unroll
            for (int ni = 0; ni < 8; ni++) {
                uint2 b = *(const uint2*)&Vb[(ni*4 + half_id*2 + p)*64 + 2*lane];
                mma16(oacc[ni], pa[p], b.x, b.y);
            }

        if (more) CP_WAIT0();   // next tile (and Wp, first time) now resident
        __syncthreads();
    }

    // ---- reduce l across lanes, then merge the two column halves ----
    lAr += __shfl_xor_sync(0xffffffffu, lAr, 1);
    lAr += __shfl_xor_sync(0xffffffffu, lAr, 2);
    lBr += __shfl_xor_sync(0xffffffffu, lBr, 1);
    lBr += __shfl_xor_sync(0xffffffffu, lBr, 2);
    if ((lane & 3) == 0) {
        lsh[rA*2 + half_id] = lAr;
        lsh[rB*2 + half_id] = lBr;
    }
    bar64(barid);
    float iA = 1.0f / (lsh[rA*2] + lsh[rA*2 + 1]);
    float iB = 1.0f / (lsh[rB*2] + lsh[rB*2 + 1]);

    float* sc = scr + mt*1024;
    if (half_id) {
#pragma unroll
        for (int ni = 0; ni < 8; ni++) {
            sc[(ni*4 + 0)*32 + lane] = oacc[ni][0];
            sc[(ni*4 + 1)*32 + lane] = oacc[ni][1];
            sc[(ni*4 + 2)*32 + lane] = oacc[ni][2];
            sc[(ni*4 + 3)*32 + lane] = oacc[ni][3];
        }
    }
    bar64(barid);
    if (!half_id) {
#pragma unroll
        for (int ni = 0; ni < 8; ni++) {
            int d0 = ni*8 + 2*(lane & 3);
            float v0 = (oacc[ni][0] + sc[(ni*4 + 0)*32 + lane]) * iA;
            float v1 = (oacc[ni][1] + sc[(ni*4 + 1)*32 + lane]) * iA;
            float v2 = (oacc[ni][2] + sc[(ni*4 + 2)*32 + lane]) * iB;
            float v3 = (oacc[ni][3] + sc[(ni*4 + 3)*32 + lane]) * iB;
            Ps[a_addr(mt*16 + rl,     d0)] = f2h2(v0, v1);
            Ps[a_addr(mt*16 + rl + 8, d0)] = f2h2(v2, v3);
        }
    }
    CP_WAIT0();          // Wp_eff copies complete (qt=0 blocks reach here early)
    __syncthreads();     // all threads' copies + Ps visible

    // ---- FUSED PROJECTION: out[64,1024] = ho @ Wp_eff + bp ----
    const int rowG = (int)qrb * 64;
#pragma unroll
    for (int mt2 = 0; mt2 < 4; mt2++) {
        unsigned a[4][4];
#pragma unroll
        for (int kt = 0; kt < 4; kt++) {
            uint4 v = *(const uint4*)&Ps[(mt2*4 + kt)*132 + aswz(lane)*4];
            a[kt][0] = v.x; a[kt][1] = v.y; a[kt][2] = v.z; a[kt][3] = v.w;
        }
        const int row = rowG + mt2*16 + (lane >> 2);
#pragma unroll
        for (int nt = 0; nt < 16; nt++) {
            float acc[4] = {0.f, 0.f, 0.f, 0.f};
#pragma unroll
            for (int kt = 0; kt < 4; kt++) {
                uint2 b = *(const uint2*)&Wps[(w*16 + nt)*256 + kt*64 + 2*lane];
                mma16(acc, a[kt], b.x, b.y);
            }
            const int col = w*128 + nt*8 + 2*(lane & 3);
            float2 bias = *(const float2*)&bias_sh[col];
            *(float2*)&out[(size_t)row*CC + col] =
                make_float2(acc[0] + bias.x, acc[1] + bias.y);
            *(float2*)&out[(size_t)(row + 8)*CC + col] =
                make_float2(acc[2] + bias.x, acc[3] + bias.y);
        }
    }
}

// ---------------------------------------------------------------------------
// Launch
// ---------------------------------------------------------------------------
extern "C" void kernel_launch(void* const* d_in, const int* in_sizes, int n_in,
                              void* d_out, int out_size) {
    const float* x  = (const float*)d_in[0];
    const float* Wq = (const float*)d_in[1];
    const float* Wk = (const float*)d_in[2];
    const float* Wv = (const float*)d_in[3];
    const float* Wp = (const float*)d_in[4];
    const float* bp = (const float*)d_in[5];
    float* out = (float*)d_out;

    const int qkv_smem  = 8320 * 4;     // 33280 B
    const int attn_smem = 44224 * 4;    // 176896 B

    cudaFuncSetAttribute(qkv_kernel,  cudaFuncAttributeMaxDynamicSharedMemorySize, qkv_smem);
    cudaFuncSetAttribute(attn_kernel, cudaFuncAttributeMaxDynamicSharedMemorySize, attn_smem);

    prep_kernel<<<256, 256>>>(Wq, Wk, Wv, Wp);
    qkv_kernel<<<MM/64, 256, qkv_smem>>>(x);
    attn_kernel<<<256, 256, attn_smem>>>(out, bp);
}

// round 16
// speedup vs baseline: 1.0255x; 1.0255x over previous
#include <cuda_runtime.h>
#include <cuda_fp16.h>
#include <math.h>

// Problem constants
#define BB 8
#define TT 2048
#define CC 1024
#define DD 64
#define MM (BB*TT)          // 16384 rows

// ---------------------------------------------------------------------------
// Global scratch, all fp16 fragment layouts (allocation-free __device__)
// A-frag (m16k16, 128 u32/tile); B-frag (k16n8, 64 u32/tile)
// ---------------------------------------------------------------------------
__device__ unsigned g_qf [MM*DD/2];   // q,  A-frag per 64-token block (scale*log2e folded)
__device__ unsigned g_kf [MM*DD/2];   // k,  B-frag: [tb][(keyTile8)(dTile4)][64]   (k=d,n=key)
__device__ unsigned g_vf [MM*DD/2];   // v,  B-frag: [tb][(dTile8)(keyTile4)][64]   (k=key,n=d)
__device__ unsigned g_wpef[DD*CC/2];      // Wp_eff: [nt(128)][kt(4)][64]
__device__ unsigned g_wqkvf[3*CC*DD/2];   // W q|k|v: [ktG(64)][mat*8+nt(24)][64]

// ---------------------------------------------------------------------------
// helpers
// ---------------------------------------------------------------------------
__device__ __forceinline__ unsigned f2h2(float a, float b) {
    __half2 h = __float22half2_rn(make_float2(a, b));
    return *reinterpret_cast<unsigned*>(&h);
}
__device__ __forceinline__ float ex2(float x) {
    float y; asm("ex2.approx.f32 %0, %1;" : "=f"(y) : "f"(x)); return y;
}
__device__ __forceinline__ void mma16(float* d, const unsigned* a, unsigned b0, unsigned b1) {
    asm volatile("mma.sync.aligned.m16n8k16.row.col.f32.f16.f16.f32 "
                 "{%0,%1,%2,%3},{%4,%5,%6,%7},{%8,%9},{%0,%1,%2,%3};"
                 : "+f"(d[0]), "+f"(d[1]), "+f"(d[2]), "+f"(d[3])
                 : "r"(a[0]), "r"(a[1]), "r"(a[2]), "r"(a[3]), "r"(b0), "r"(b1));
}
__device__ __forceinline__ int aswz(int L) { return L ^ (L >> 3); }
// A-frag u32 address within a 64row x 64k block (4x4 tiles of 132 u, swizzled)
__device__ __forceinline__ int a_addr(int row, int k) {    // k even
    return ((row >> 4)*4 + (k >> 4)) * 132
         + aswz(((row & 7) << 2) | ((k >> 1) & 3)) * 4
         + ((row >> 3) & 1) + (((k >> 3) & 1) << 1);
}
__device__ __forceinline__ int bf_idx(int k, int n) {      // k even
    return ((((n & 7) << 2) | ((k >> 1) & 3)) << 1) + ((k >> 3) & 1);
}
__device__ __forceinline__ void bar64(int id) {
    asm volatile("bar.sync %0, %1;" :: "r"(id), "r"(64) : "memory");
}
__device__ __forceinline__ void cpa16(unsigned saddr, const void* g) {
    asm volatile("cp.async.cg.shared.global [%0], [%1], 16;" :: "r"(saddr), "l"(g));
}
#define CP_COMMIT() asm volatile("cp.async.commit_group;" ::: "memory")
#define CP_WAIT0()  asm volatile("cp.async.wait_group 0;" ::: "memory")

// ---------------------------------------------------------------------------
// Kernel 1 (prep_w): ONLY the q/k/v weight conversion (small, ~0.75 MB read).
// The Wp fold moved into qkv's extra blocks (it is consumed only by attn).
// 32768 threads; each handles one (c-pair, n) of all three weights.
// ---------------------------------------------------------------------------
__global__ __launch_bounds__(256) void prep_w_kernel(const float* __restrict__ Wq,
                                                     const float* __restrict__ Wk,
                                                     const float* __restrict__ Wv) {
    int pid = blockIdx.x * 256 + threadIdx.x;      // 0..32767
    const float qs = 0.03125f * 1.44269504088896f;
    int c0 = (pid >> 6) * 2, n = pid & 63;
    int ba = (c0 >> 4)*1536 + (n >> 3)*64 + bf_idx(c0, n);
    g_wqkvf[ba]        = f2h2(Wq[c0*64 + n]*qs, Wq[(c0+1)*64 + n]*qs);
    g_wqkvf[ba + 512]  = f2h2(Wk[c0*64 + n],    Wk[(c0+1)*64 + n]);
    g_wqkvf[ba + 1024] = f2h2(Wv[c0*64 + n],    Wv[(c0+1)*64 + n]);
}

// ---------------------------------------------------------------------------
// Kernel 2: fused QKV (R10 mainloop) + 32 TRAILING BLOCKS doing the Wp fold
// concurrently (g_wpef is consumed only by the NEXT kernel). Grid 288.
// ---------------------------------------------------------------------------
__global__ __launch_bounds__(256, 2) void qkv_kernel(const float* __restrict__ x,
                                                     const float* __restrict__ Wp) {
    extern __shared__ unsigned smu[];
    const int t = threadIdx.x, lane = t & 31, w = t >> 5;

    // ---- trailing blocks: Wp_eff fold (runs concurrently with the GEMM) ----
    if (blockIdx.x >= 256) {
        int g = (blockIdx.x - 256)*256 + t;        // 0..8191
#pragma unroll
        for (int pq = 0; pq < 4; pq++) {
            int pid = g*4 + pq;                    // 0..32767
            int d0 = (pid >> 10) * 2, j = pid & 1023;
            float s0 = 0.f, s1 = 0.f;
#pragma unroll
            for (int h = 0; h < 16; h++) {
                s0 += Wp[(h*64 + d0    )*1024 + j];
                s1 += Wp[(h*64 + d0 + 1)*1024 + j];
            }
            g_wpef[(j >> 3)*256 + (d0 >> 4)*64 + bf_idx(d0, j)] = f2h2(s0, s1);
        }
        return;
    }

    const int rowBase = blockIdx.x * 64;
    const int m0t = (w & 1) * 2;
    const int ntb = (w >> 1) * 6;

    float acc[2][6][4];
#pragma unroll
    for (int mi = 0; mi < 2; mi++)
#pragma unroll
        for (int ni = 0; ni < 6; ni++)
#pragma unroll
            for (int r = 0; r < 4; r++) acc[mi][ni][r] = 0.f;

    const int arow = t >> 2, acol4 = (t & 3) * 4;
    float4 xr[4];
#pragma unroll
    for (int q = 0; q < 4; q++)
        xr[q] = *(const float4*)&x[(size_t)(rowBase + arow)*CC + q*16 + acol4];
#pragma unroll
    for (int q = 0; q < 4; q++) {
        int k = q*16 + acol4;
        smu[a_addr(arow, k)]     = f2h2(xr[q].x, xr[q].y);
        smu[a_addr(arow, k + 2)] = f2h2(xr[q].z, xr[q].w);
    }
    __syncthreads();

    for (int k0 = 0; k0 < CC; k0 += 64) {
        const unsigned* As = smu + ((k0 >> 6) & 1) * 2112;
        const int ktG = k0 >> 4;
        const bool more = (k0 + 64) < CC;
        if (more) {
#pragma unroll
            for (int q = 0; q < 4; q++)
                xr[q] = *(const float4*)&x[(size_t)(rowBase + arow)*CC + k0 + 64 + q*16 + acol4];
        }
#pragma unroll
        for (int ks = 0; ks < 4; ks++) {
            uint4 v0 = *(const uint4*)&As[(m0t*4 + ks)*132 + aswz(lane)*4];
            uint4 v1 = *(const uint4*)&As[((m0t+1)*4 + ks)*132 + aswz(lane)*4];
            unsigned a0[4] = {v0.x, v0.y, v0.z, v0.w};
            unsigned a1[4] = {v1.x, v1.y, v1.z, v1.w};
#pragma unroll
            for (int ni = 0; ni < 6; ni++) {
                uint2 b = *(const uint2*)&g_wqkvf[(ktG + ks)*1536 + (ntb + ni)*64 + 2*lane];
                mma16(acc[0][ni], a0, b.x, b.y);
                mma16(acc[1][ni], a1, b.x, b.y);
            }
        }
        if (more) {
            unsigned* An = smu + (((k0 >> 6) & 1) ^ 1) * 2112;
#pragma unroll
            for (int q = 0; q < 4; q++) {
                int k = q*16 + acol4;
                An[a_addr(arow, k)]     = f2h2(xr[q].x, xr[q].y);
                An[a_addr(arow, k + 2)] = f2h2(xr[q].z, xr[q].w);
            }
        }
        __syncthreads();
    }

    // ---- epilogue: stage C-frags into fp16 operand layouts ----
    __half* vstage = (__half*)(smu + 6272);
#pragma unroll
    for (int mi = 0; mi < 2; mi++) {
#pragma unroll
        for (int ni = 0; ni < 6; ni++) {
            int row0 = (w & 1)*32 + mi*16 + (lane >> 2);
            int col0 = (ntb + ni)*8 + 2*(lane & 3);
            int mat = col0 >> 6;
            if (mat == 0) {
                smu[a_addr(row0,     col0)] = f2h2(acc[mi][ni][0], acc[mi][ni][1]);
                smu[a_addr(row0 + 8, col0)] = f2h2(acc[mi][ni][2], acc[mi][ni][3]);
            } else if (mat == 1) {
                int d = col0 - 64;
                int t0 = ((row0 >> 3)*4 + (d >> 4))*64;
                smu[4224 + t0       + bf_idx(d, row0)] = f2h2(acc[mi][ni][0], acc[mi][ni][1]);
                smu[4224 + t0 + 256 + bf_idx(d, row0)] = f2h2(acc[mi][ni][2], acc[mi][ni][3]);
            } else {
                int d = col0 - 128;
                int u0 = (d >> 3)*256 + (row0 >> 4)*64;
                vstage[(u0 + bf_idx(row0 & 63, d))*2     + (row0 & 1)] = __float2half_rn(acc[mi][ni][0]);
                vstage[(u0 + bf_idx(row0 & 63, d+1))*2   + (row0 & 1)] = __float2half_rn(acc[mi][ni][1]);
                int r8 = row0 + 8;
                int u8 = (d >> 3)*256 + (r8 >> 4)*64;
                vstage[(u8 + bf_idx(r8 & 63, d))*2   + (r8 & 1)] = __float2half_rn(acc[mi][ni][2]);
                vstage[(u8 + bf_idx(r8 & 63, d+1))*2 + (r8 & 1)] = __float2half_rn(acc[mi][ni][3]);
            }
        }
    }
    __syncthreads();

    const size_t rb = blockIdx.x;
#pragma unroll
    for (int j = 0; j < 2; j++) {
        int tile = w*2 + j;
        uint4 v = *(const uint4*)&smu[tile*132 + aswz(lane)*4];
        *(uint4*)&g_qf[rb*2048 + tile*128 + lane*4] = v;
    }
#pragma unroll
    for (int j = 0; j < 2; j++) {
        int u = t + 256*j;
        *(uint4*)&g_kf[rb*2048 + 4*u] = *(const uint4*)&smu[4224 + 4*u];
    }
#pragma unroll
    for (int j = 0; j < 2; j++) {
        int u = t + 256*j;
        *(uint4*)&g_vf[rb*2048 + 4*u] = *(const uint4*)&smu[6272 + 4*u];
    }
}

// ---------------------------------------------------------------------------
// Kernel 3: causal flash attention + FUSED PROJECTION (EXACT R14 winner).
// Mainloop R10 (no-max softmax, register P, reg-prefetch KV, 1 sync/tile,
// unpaired LPT grid 256 blocks). Wp_eff (128 KB) streamed into smem via
// fire-and-forget cp.async at start, waited only before the epilogue.
// smem (u32): K 0/2048, V 4096/6144, Ps @8192 (2112), lsh @10304 (128),
//             Wps @10432 (32768), bias @43200 (1024). total 44224 u32.
// ---------------------------------------------------------------------------
__global__ __launch_bounds__(256, 1) void attn_kernel(float* __restrict__ out,
                                                      const float* __restrict__ bp) {
    extern __shared__ unsigned smu[];
    unsigned* Ps = smu + 8192;
    float* lsh = (float*)(smu + 10304);
    unsigned* Wps = smu + 10432;
    float* bias_sh = (float*)(smu + 43200);
    float* scr = (float*)smu;

    const int t = threadIdx.x, lane = t & 31, w = t >> 5;
    const int bid = blockIdx.x;
    const int batch = bid & 7;
    const int qt = 31 - (bid >> 3);       // big q-tiles first (LPT)
    const int half_id = w & 1;
    const int mt = w >> 1;
    const int rl = lane >> 2;
    const int rA = mt*16 + rl, rB = rA + 8;
    const int colb = half_id * 32;
    const int barid = 1 + mt;

    const size_t qrb = batch*32 + qt;
    const int ntiles = qt + 1;

    // fire-and-forget: Wp_eff gmem -> smem (32 x 16B per thread), waited later
    {
        const unsigned wbase = (unsigned)__cvta_generic_to_shared(Wps);
#pragma unroll
        for (int j = 0; j < 32; j++) {
            int u = t + 256*j;            // uint4 index, 0..8191
            cpa16(wbase + u*16, &g_wpef[4*u]);
        }
        CP_COMMIT();
    }
    // bias -> smem
    *(float4*)&bias_sh[t*4] = *(const float4*)&bp[t*4];

    // Q fragments: gmem -> registers (4 k16 tiles)
    unsigned qf[4][4];
#pragma unroll
    for (int kt = 0; kt < 4; kt++) {
        uint4 v = *(const uint4*)&g_qf[qrb*2048 + (mt*4 + kt)*128 + lane*4];
        qf[kt][0] = v.x; qf[kt][1] = v.y; qf[kt][2] = v.z; qf[kt][3] = v.w;
    }
    // prefetch + store KV tile 0
    uint4 kr[2], vr[2];
    {
        size_t tb = batch*32;
#pragma unroll
        for (int j = 0; j < 2; j++) {
            kr[j] = *(const uint4*)&g_kf[tb*2048 + 4*(t + 256*j)];
            vr[j] = *(const uint4*)&g_vf[tb*2048 + 4*(t + 256*j)];
        }
    }
#pragma unroll
    for (int j = 0; j < 2; j++) {
        *(uint4*)&smu[4*(t + 256*j)]        = kr[j];
        *(uint4*)&smu[4096 + 4*(t + 256*j)] = vr[j];
    }

    float lAr = 0.f, lBr = 0.f;
    float oacc[8][4];
#pragma unroll
    for (int ni = 0; ni < 8; ni++)
#pragma unroll
        for (int r = 0; r < 4; r++) oacc[ni][r] = 0.f;
    __syncthreads();

    for (int it = 0; it < ntiles; it++) {
        const unsigned* Kb = smu + (it & 1)*2048;
        const unsigned* Vb = smu + 4096 + (it & 1)*2048;

        float sacc[4][4];
#pragma unroll
        for (int ni = 0; ni < 4; ni++)
#pragma unroll
            for (int r = 0; r < 4; r++) sacc[ni][r] = 0.f;
#pragma unroll
        for (int ks = 0; ks < 4; ks++)
#pragma unroll
            for (int ni = 0; ni < 4; ni++) {
                uint2 b = *(const uint2*)&Kb[((half_id*4 + ni)*4 + ks)*64 + 2*lane];
                mma16(sacc[ni], qf[ks], b.x, b.y);
            }

        const bool more = (it + 1) < ntiles;
        if (more) {
            size_t tb = batch*32 + it + 1;
#pragma unroll
            for (int j = 0; j < 2; j++) {
                kr[j] = *(const uint4*)&g_kf[tb*2048 + 4*(t + 256*j)];
                vr[j] = *(const uint4*)&g_vf[tb*2048 + 4*(t + 256*j)];
            }
        }

        if (it == ntiles - 1) {
#pragma unroll
            for (int ni = 0; ni < 4; ni++) {
                int c0 = colb + ni*8 + 2*(lane & 3);
                if (c0     > rA) sacc[ni][0] = -1e30f;
                if (c0 + 1 > rA) sacc[ni][1] = -1e30f;
                if (c0     > rB) sacc[ni][2] = -1e30f;
                if (c0 + 1 > rB) sacc[ni][3] = -1e30f;
            }
        }

        unsigned pa[2][4];
#pragma unroll
        for (int ni = 0; ni < 4; ni++) {
            float p0 = ex2(sacc[ni][0]);
            float p1 = ex2(sacc[ni][1]);
            float p2 = ex2(sacc[ni][2]);
            float p3 = ex2(sacc[ni][3]);
            lAr += p0 + p1;
            lBr += p2 + p3;
            pa[ni >> 1][(ni & 1)*2]     = f2h2(p0, p1);
            pa[ni >> 1][(ni & 1)*2 + 1] = f2h2(p2, p3);
        }

#pragma unroll
        for (int p = 0; p < 2; p++)
#pragma unroll
            for (int ni = 0; ni < 8; ni++) {
                uint2 b = *(const uint2*)&Vb[(ni*4 + half_id*2 + p)*64 + 2*lane];
                mma16(oacc[ni], pa[p], b.x, b.y);
            }

        if (more) {
            unsigned nb = ((it + 1) & 1) * 2048;
#pragma unroll
            for (int j = 0; j < 2; j++) {
                *(uint4*)&smu[nb + 4*(t + 256*j)]        = kr[j];
                *(uint4*)&smu[4096 + nb + 4*(t + 256*j)] = vr[j];
            }
        }
        __syncthreads();
    }

    // ---- reduce l across lanes, then merge the two column halves ----
    lAr += __shfl_xor_sync(0xffffffffu, lAr, 1);
    lAr += __shfl_xor_sync(0xffffffffu, lAr, 2);
    lBr += __shfl_xor_sync(0xffffffffu, lBr, 1);
    lBr += __shfl_xor_sync(0xffffffffu, lBr, 2);
    if ((lane & 3) == 0) {
        lsh[rA*2 + half_id] = lAr;
        lsh[rB*2 + half_id] = lBr;
    }
    bar64(barid);
    float iA = 1.0f / (lsh[rA*2] + lsh[rA*2 + 1]);
    float iB = 1.0f / (lsh[rB*2] + lsh[rB*2 + 1]);

    float* sc = scr + mt*1024;
    if (half_id) {
#pragma unroll
        for (int ni = 0; ni < 8; ni++) {
            sc[(ni*4 + 0)*32 + lane] = oacc[ni][0];
            sc[(ni*4 + 1)*32 + lane] = oacc[ni][1];
            sc[(ni*4 + 2)*32 + lane] = oacc[ni][2];
            sc[(ni*4 + 3)*32 + lane] = oacc[ni][3];
        }
    }
    bar64(barid);
    if (!half_id) {
#pragma unroll
        for (int ni = 0; ni < 8; ni++) {
            int d0 = ni*8 + 2*(lane & 3);
            float v0 = (oacc[ni][0] + sc[(ni*4 + 0)*32 + lane]) * iA;
            float v1 = (oacc[ni][1] + sc[(ni*4 + 1)*32 + lane]) * iA;
            float v2 = (oacc[ni][2] + sc[(ni*4 + 2)*32 + lane]) * iB;
            float v3 = (oacc[ni][3] + sc[(ni*4 + 3)*32 + lane]) * iB;
            Ps[a_addr(mt*16 + rl,     d0)] = f2h2(v0, v1);
            Ps[a_addr(mt*16 + rl + 8, d0)] = f2h2(v2, v3);
        }
    }
    CP_WAIT0();          // Wp_eff copies complete (own thread's)
    __syncthreads();     // all threads' copies + Ps visible

    // ---- FUSED PROJECTION: out[64,1024] = ho @ Wp_eff + bp ----
    const int rowG = (int)qrb * 64;
#pragma unroll
    for (int mt2 = 0; mt2 < 4; mt2++) {
        unsigned a[4][4];
#pragma unroll
        for (int kt = 0; kt < 4; kt++) {
            uint4 v = *(const uint4*)&Ps[(mt2*4 + kt)*132 + aswz(lane)*4];
            a[kt][0] = v.x; a[kt][1] = v.y; a[kt][2] = v.z; a[kt][3] = v.w;
        }
        const int row = rowG + mt2*16 + (lane >> 2);
#pragma unroll
        for (int nt = 0; nt < 16; nt++) {
            float acc[4] = {0.f, 0.f, 0.f, 0.f};
#pragma unroll
            for (int kt = 0; kt < 4; kt++) {
                uint2 b = *(const uint2*)&Wps[(w*16 + nt)*256 + kt*64 + 2*lane];
                mma16(acc, a[kt], b.x, b.y);
            }
            const int col = w*128 + nt*8 + 2*(lane & 3);
            float2 bias = *(const float2*)&bias_sh[col];
            *(float2*)&out[(size_t)row*CC + col] =
                make_float2(acc[0] + bias.x, acc[1] + bias.y);
            *(float2*)&out[(size_t)(row + 8)*CC + col] =
                make_float2(acc[2] + bias.x, acc[3] + bias.y);
        }
    }
}

// ---------------------------------------------------------------------------
// Launch
// ---------------------------------------------------------------------------
extern "C" void kernel_launch(void* const* d_in, const int* in_sizes, int n_in,
                              void* d_out, int out_size) {
    const float* x  = (const float*)d_in[0];
    const float* Wq = (const float*)d_in[1];
    const float* Wk = (const float*)d_in[2];
    const float* Wv = (const float*)d_in[3];
    const float* Wp = (const float*)d_in[4];
    const float* bp = (const float*)d_in[5];
    float* out = (float*)d_out;

    const int qkv_smem  = 8320 * 4;     // 33280 B
    const int attn_smem = 44224 * 4;    // 176896 B

    cudaFuncSetAttribute(qkv_kernel,  cudaFuncAttributeMaxDynamicSharedMemorySize, qkv_smem);
    cudaFuncSetAttribute(attn_kernel, cudaFuncAttributeMaxDynamicSharedMemorySize, attn_smem);

    prep_w_kernel<<<128, 256>>>(Wq, Wk, Wv);
    qkv_kernel<<<288, 256, qkv_smem>>>(x, Wp);
    attn_kernel<<<256, 256, attn_smem>>>(out, bp);
}